// round 5
// baseline (speedup 1.0000x reference)
#include <cuda_runtime.h>
#include <cuda_bf16.h>
#include <cstdint>
#include <math.h>

// ---------------------------------------------------------------------------
// ACM-GCN on GB300, round 5.
//  - layer1: spmm_cvt (gather x, unroll8) -> gemm_mma<128> -> att_fuse
//            (attention combine + relu + DIRECT split-bf16 emit; conv_x gone)
//  - layer2: gemm_mma<64> writes low|high interleaved into one [N,128] buffer
//            -> acm_fuse64 gathers 512B/neighbor in ONE float4/lane (unroll8),
//            halves recombined via shfl_xor(16).
//  - scan: thread-coarsened single-block scan (98 elem/thread).
// ---------------------------------------------------------------------------

#define MAXN 100000
#define MAXE 1600000

__device__ int   g_deg[MAXN];
__device__ int   g_fill[MAXN];
__device__ int   g_rowptr[MAXN + 1];
__device__ int   g_col[MAXE];
__device__ float g_hl[(size_t)MAXN * 128];   // layer1: low out; layer2: low|high interleaved
__device__ float g_hh[(size_t)MAXN * 128];
__device__ float g_hm[(size_t)MAXN * 128];
__device__ __nv_bfloat16 g_ahi[(size_t)MAXN * 128];
__device__ __nv_bfloat16 g_alo[(size_t)MAXN * 128];
__device__ __nv_bfloat16 g_bhi[(size_t)MAXN * 128];
__device__ __nv_bfloat16 g_blo[(size_t)MAXN * 128];
__device__ __nv_bfloat16 g_chi[(size_t)MAXN * 128];
__device__ __nv_bfloat16 g_clo[(size_t)MAXN * 128];
__device__ __nv_bfloat16 g_wthi[3 * 128 * 128];
__device__ __nv_bfloat16 g_wtlo[3 * 128 * 128];

__device__ __forceinline__ uint32_t smem_u32(const void* p) {
    uint32_t a;
    asm("{ .reg .u64 t; cvta.to.shared.u64 t, %1; cvt.u32.u64 %0, t; }"
        : "=r"(a) : "l"(p));
    return a;
}

// --------------------------- CSR construction -----------------------------

__global__ void zero_kernel(int* deg, int* fill, int n) {
    int i = blockIdx.x * blockDim.x + threadIdx.x;
    if (i < n) { deg[i] = 0; fill[i] = 0; }
}

__global__ void deg_kernel(const int* __restrict__ row, int* deg, int E) {
    int e = blockIdx.x * blockDim.x + threadIdx.x;
    if (e < E) atomicAdd(&deg[row[e]], 1);
}

// thread-coarsened single-block exclusive scan
__global__ void scan_kernel(const int* __restrict__ deg, int* __restrict__ rowptr, int n) {
    __shared__ int wsum[32];
    const int tid = threadIdx.x, lane = tid & 31, w = tid >> 5;
    const int CH = (n + 1023) >> 10;
    const int s = tid * CH;
    const int eL = min(s + CH, n);

    int sum = 0;
    for (int i = s; i < eL; i++) sum += deg[i];

    int x = sum;
    #pragma unroll
    for (int o = 1; o < 32; o <<= 1) {
        int y = __shfl_up_sync(0xffffffffu, x, o);
        if (lane >= o) x += y;
    }
    if (lane == 31) wsum[w] = x;
    __syncthreads();
    if (w == 0) {
        int t = wsum[lane];
        #pragma unroll
        for (int o = 1; o < 32; o <<= 1) {
            int y = __shfl_up_sync(0xffffffffu, t, o);
            if (lane >= o) t += y;
        }
        wsum[lane] = t;
    }
    __syncthreads();

    int run = (w > 0 ? wsum[w - 1] : 0) + x - sum;  // exclusive prefix for this thread
    for (int i = s; i < eL; i++) { rowptr[i] = run; run += deg[i]; }
    if (s < n && eL == n) rowptr[n] = run;
}

__global__ void scatter_kernel(const int* __restrict__ row, const int* __restrict__ colsrc,
                               const int* __restrict__ rowptr, int* fill,
                               int* __restrict__ colout, int E) {
    int e = blockIdx.x * blockDim.x + threadIdx.x;
    if (e < E) {
        int r = row[e];
        int p = rowptr[r] + atomicAdd(&fill[r], 1);
        colout[p] = colsrc[e];
    }
}

// ----------------------- split-bf16 helpers --------------------------------

__device__ __forceinline__ void split4(const float* v, uint2& hv, uint2& lv) {
    __nv_bfloat16 h0 = __float2bfloat16(v[0]), h1 = __float2bfloat16(v[1]);
    __nv_bfloat16 h2 = __float2bfloat16(v[2]), h3 = __float2bfloat16(v[3]);
    __nv_bfloat16 l0 = __float2bfloat16(v[0] - __bfloat162float(h0));
    __nv_bfloat16 l1 = __float2bfloat16(v[1] - __bfloat162float(h1));
    __nv_bfloat16 l2 = __float2bfloat16(v[2] - __bfloat162float(h2));
    __nv_bfloat16 l3 = __float2bfloat16(v[3] - __bfloat162float(h3));
    __nv_bfloat162 hp0(h0, h1), hp1(h2, h3), lp0(l0, l1), lp1(l2, l3);
    hv.x = *(uint32_t*)&hp0; hv.y = *(uint32_t*)&hp1;
    lv.x = *(uint32_t*)&lp0; lv.y = *(uint32_t*)&lp1;
}

// W[k][n] row-major -> Wt[y][n][k] split bf16
__global__ void conv_w_kernel(const float* __restrict__ W0, const float* __restrict__ W1,
                              const float* __restrict__ W2,
                              __nv_bfloat16* __restrict__ hi, __nv_bfloat16* __restrict__ lo,
                              int K, int Nn) {
    int id = blockIdx.x * blockDim.x + threadIdx.x;
    int tot = 3 * K * Nn;
    if (id >= tot) return;
    int y = id / (K * Nn);
    int rem = id - y * K * Nn;
    int k = rem / Nn;
    int n = rem - k * Nn;
    const float* W = (y == 0) ? W0 : (y == 1) ? W1 : W2;
    float w = W[k * Nn + n];
    __nv_bfloat16 h = __float2bfloat16(w);
    __nv_bfloat16 l = __float2bfloat16(w - __bfloat162float(h));
    hi[(size_t)y * Nn * K + n * K + k] = h;
    lo[(size_t)y * Nn * K + n * K + k] = l;
}

// -------------------- layer-1 spmm + split converts ------------------------

__global__ __launch_bounds__(256)
void spmm_cvt(const float* __restrict__ x,
              const int* __restrict__ rowptr, const int* __restrict__ col,
              __nv_bfloat16* __restrict__ Ahi, __nv_bfloat16* __restrict__ Alo,
              __nv_bfloat16* __restrict__ Bhi, __nv_bfloat16* __restrict__ Blo,
              __nv_bfloat16* __restrict__ Chi, __nv_bfloat16* __restrict__ Clo,
              int n) {
    int gw = (blockIdx.x * blockDim.x + threadIdx.x) >> 5;
    if (gw >= n) return;
    const int lane = threadIdx.x & 31;
    const int s = rowptr[gw], e = rowptr[gw + 1];

    float acc[4] = {0.f, 0.f, 0.f, 0.f};

    for (int base = s; base < e; base += 32) {
        int idx = base + lane;
        int c = (idx < e) ? col[idx] : 0;
        int cnt = min(32, e - base);
        int k = 0;
        for (; k + 8 <= cnt; k += 8) {
            float4 v[8];
            #pragma unroll
            for (int j = 0; j < 8; j++) {
                int cc = __shfl_sync(0xffffffffu, c, k + j);
                v[j] = *(const float4*)(x + (size_t)cc * 128 + lane * 4);
            }
            #pragma unroll
            for (int j = 0; j < 8; j++) {
                acc[0] += v[j].x; acc[1] += v[j].y; acc[2] += v[j].z; acc[3] += v[j].w;
            }
        }
        for (; k < cnt; k++) {
            int cc = __shfl_sync(0xffffffffu, c, k);
            float4 v = *(const float4*)(x + (size_t)cc * 128 + lane * 4);
            acc[0] += v.x; acc[1] += v.y; acc[2] += v.z; acc[3] += v.w;
        }
    }

    const float inv = (e > s) ? 1.0f / (float)(e - s) : 0.0f;
    float4 hrow = *(const float4*)(x + (size_t)gw * 128 + lane * 4);

    float agg[4], dif[4], own[4] = {hrow.x, hrow.y, hrow.z, hrow.w};
    #pragma unroll
    for (int i = 0; i < 4; i++) {
        agg[i] = inv * acc[i];
        dif[i] = own[i] - agg[i];
    }

    const size_t off = ((size_t)gw * 128 + lane * 4) / 4;
    uint2 hv, lv;
    split4(agg, hv, lv); ((uint2*)Ahi)[off] = hv; ((uint2*)Alo)[off] = lv;
    split4(dif, hv, lv); ((uint2*)Bhi)[off] = hv; ((uint2*)Blo)[off] = lv;
    split4(own, hv, lv); ((uint2*)Chi)[off] = hv; ((uint2*)Clo)[off] = lv;
}

// ------------------------- mma.sync GEMM -----------------------------------
// C[y] = A[y][M,128] @ W[y] (B[NB,128] K-major), split-bf16, fp32 accumulate.
// Per-branch output pointer / leading dim / column offset.

template <int NB>
__global__ __launch_bounds__(256, 1)
void gemm_mma(const __nv_bfloat16* __restrict__ A0hi, const __nv_bfloat16* __restrict__ A0lo,
              const __nv_bfloat16* __restrict__ A1hi, const __nv_bfloat16* __restrict__ A1lo,
              const __nv_bfloat16* __restrict__ A2hi, const __nv_bfloat16* __restrict__ A2lo,
              const __nv_bfloat16* __restrict__ Bhi, const __nv_bfloat16* __restrict__ Blo,
              float* __restrict__ C0, float* __restrict__ C1, float* __restrict__ C2,
              int ld0, int ld1, int ld2, int off0, int off1, int off2,
              int M, int reluAll) {
    constexpr int SA = 136;
    constexpr int WN = NB / 4;
    constexpr int NT = WN / 8;

    extern __shared__ __align__(16) char smem[];
    __nv_bfloat16* sAhi = (__nv_bfloat16*)smem;
    __nv_bfloat16* sAlo = sAhi + 128 * SA;
    __nv_bfloat16* sBhi = sAlo + 128 * SA;
    __nv_bfloat16* sBlo = sBhi + NB * SA;

    const int tid = threadIdx.x, wid = tid >> 5, lane = tid & 31;
    const int y = blockIdx.y;
    const int rowBase = blockIdx.x * 128;
    const __nv_bfloat16* Ahi = (y == 0) ? A0hi : (y == 1) ? A1hi : A2hi;
    const __nv_bfloat16* Alo = (y == 0) ? A0lo : (y == 1) ? A1lo : A2lo;
    const __nv_bfloat16* bh = Bhi + (size_t)y * NB * 128;
    const __nv_bfloat16* bl = Blo + (size_t)y * NB * 128;

    #pragma unroll
    for (int i = tid; i < 128 * 16; i += 256) {
        int r = i >> 4, c = i & 15;
        int gr = rowBase + r;
        uint4 vh = make_uint4(0, 0, 0, 0), vl = make_uint4(0, 0, 0, 0);
        if (gr < M) {
            vh = *(const uint4*)(Ahi + (size_t)gr * 128 + c * 8);
            vl = *(const uint4*)(Alo + (size_t)gr * 128 + c * 8);
        }
        *(uint4*)(sAhi + r * SA + c * 8) = vh;
        *(uint4*)(sAlo + r * SA + c * 8) = vl;
    }
    #pragma unroll
    for (int i = tid; i < NB * 16; i += 256) {
        int r = i >> 4, c = i & 15;
        *(uint4*)(sBhi + r * SA + c * 8) = *(const uint4*)(bh + r * 128 + c * 8);
        *(uint4*)(sBlo + r * SA + c * 8) = *(const uint4*)(bl + r * 128 + c * 8);
    }
    __syncthreads();

    const int m0 = (wid >> 2) * 64;
    const int n0 = (wid & 3) * WN;

    float acc[4][NT][4];
    #pragma unroll
    for (int mt = 0; mt < 4; mt++)
        #pragma unroll
        for (int nt = 0; nt < NT; nt++)
            #pragma unroll
            for (int j = 0; j < 4; j++) acc[mt][nt][j] = 0.0f;

    const __nv_bfloat16* pA[3] = {sAhi, sAhi, sAlo};
    const __nv_bfloat16* pB[3] = {sBhi, sBlo, sBhi};

    const int aj = lane >> 3;
    const int aRow = ((aj & 1) << 3) + (lane & 7);
    const int aK = (aj >> 1) << 3;
    const int bRow = lane & 7;
    const int bK = ((lane >> 3) & 1) << 3;

    #pragma unroll
    for (int p = 0; p < 3; p++) {
        const uint32_t aBase = smem_u32(pA[p]);
        const uint32_t bBase = smem_u32(pB[p]);
        #pragma unroll
        for (int ks = 0; ks < 8; ks++) {
            const int k0 = ks * 16;
            uint32_t af[4][4];
            #pragma unroll
            for (int mt = 0; mt < 4; mt++) {
                uint32_t addr = aBase + (uint32_t)(((m0 + mt * 16 + aRow) * SA + k0 + aK) * 2);
                asm volatile("ldmatrix.sync.aligned.m8n8.x4.shared.b16 {%0,%1,%2,%3}, [%4];"
                             : "=r"(af[mt][0]), "=r"(af[mt][1]), "=r"(af[mt][2]), "=r"(af[mt][3])
                             : "r"(addr));
            }
            uint32_t bf[NT][2];
            #pragma unroll
            for (int nt = 0; nt < NT; nt++) {
                uint32_t addr = bBase + (uint32_t)(((n0 + nt * 8 + bRow) * SA + k0 + bK) * 2);
                asm volatile("ldmatrix.sync.aligned.m8n8.x2.shared.b16 {%0,%1}, [%2];"
                             : "=r"(bf[nt][0]), "=r"(bf[nt][1]) : "r"(addr));
            }
            #pragma unroll
            for (int mt = 0; mt < 4; mt++)
                #pragma unroll
                for (int nt = 0; nt < NT; nt++)
                    asm volatile(
                        "mma.sync.aligned.m16n8k16.row.col.f32.bf16.bf16.f32 "
                        "{%0,%1,%2,%3}, {%4,%5,%6,%7}, {%8,%9}, {%0,%1,%2,%3};"
                        : "+f"(acc[mt][nt][0]), "+f"(acc[mt][nt][1]),
                          "+f"(acc[mt][nt][2]), "+f"(acc[mt][nt][3])
                        : "r"(af[mt][0]), "r"(af[mt][1]), "r"(af[mt][2]), "r"(af[mt][3]),
                          "r"(bf[nt][0]), "r"(bf[nt][1]));
        }
    }

    const bool relu = reluAll || (y == 2);
    float* C = (y == 0) ? C0 : (y == 1) ? C1 : C2;
    const int ldC = (y == 0) ? ld0 : (y == 1) ? ld1 : ld2;
    const int cOff = (y == 0) ? off0 : (y == 1) ? off1 : off2;
    const int colBase = cOff + n0 + (lane & 3) * 2;
    const int rTop = rowBase + m0 + (lane >> 2);
    #pragma unroll
    for (int mt = 0; mt < 4; mt++) {
        int r0 = rTop + mt * 16;
        int r1 = r0 + 8;
        #pragma unroll
        for (int nt = 0; nt < NT; nt++) {
            float2 v0, v1;
            v0.x = acc[mt][nt][0]; v0.y = acc[mt][nt][1];
            v1.x = acc[mt][nt][2]; v1.y = acc[mt][nt][3];
            if (relu) {
                v0.x = fmaxf(v0.x, 0.f); v0.y = fmaxf(v0.y, 0.f);
                v1.x = fmaxf(v1.x, 0.f); v1.y = fmaxf(v1.y, 0.f);
            }
            int c = colBase + nt * 8;
            if (r0 < M) *(float2*)(C + (size_t)r0 * ldC + c) = v0;
            if (r1 < M) *(float2*)(C + (size_t)r1 * ldC + c) = v1;
        }
    }
}

// ------ layer-1 attention combine + relu + direct split-bf16 emit ----------

__global__ __launch_bounds__(256)
void att_fuse(const float* __restrict__ ol, const float* __restrict__ oh,
              const float* __restrict__ om,
              const float* __restrict__ vl, const float* __restrict__ vh,
              const float* __restrict__ vm, const float* __restrict__ av,
              __nv_bfloat16* __restrict__ Ahi, __nv_bfloat16* __restrict__ Alo,
              int n) {
    int gw = (blockIdx.x * blockDim.x + threadIdx.x) >> 5;
    if (gw >= n) return;
    const int lane = threadIdx.x & 31;
    const size_t base = (size_t)gw * 128 + lane * 4;

    float4 lo4 = *(const float4*)(ol + base);
    float4 hi4 = *(const float4*)(oh + base);
    float4 ml4 = *(const float4*)(om + base);
    float low[4] = {lo4.x, lo4.y, lo4.z, lo4.w};
    float high[4] = {hi4.x, hi4.y, hi4.z, hi4.w};
    float mlp[4] = {ml4.x, ml4.y, ml4.z, ml4.w};

    float dl = 0.f, dh = 0.f, dm = 0.f;
    #pragma unroll
    for (int i = 0; i < 4; i++) {
        dl += low[i]  * vl[lane * 4 + i];
        dh += high[i] * vh[lane * 4 + i];
        dm += mlp[i]  * vm[lane * 4 + i];
    }
    #pragma unroll
    for (int o = 16; o > 0; o >>= 1) {
        dl += __shfl_xor_sync(0xffffffffu, dl, o);
        dh += __shfl_xor_sync(0xffffffffu, dh, o);
        dm += __shfl_xor_sync(0xffffffffu, dm, o);
    }

    float sl = 1.0f / (1.0f + __expf(-dl));
    float sh = 1.0f / (1.0f + __expf(-dh));
    float sm = 1.0f / (1.0f + __expf(-dm));

    float t0 = (sl * av[0] + sh * av[3] + sm * av[6]) * (1.0f / 3.0f);
    float t1 = (sl * av[1] + sh * av[4] + sm * av[7]) * (1.0f / 3.0f);
    float t2 = (sl * av[2] + sh * av[5] + sm * av[8]) * (1.0f / 3.0f);
    float mx = fmaxf(t0, fmaxf(t1, t2));
    float w0 = __expf(t0 - mx), w1 = __expf(t1 - mx), w2 = __expf(t2 - mx);
    float wsum = w0 + w1 + w2;
    float a0 = 3.0f * w0 / wsum, a1 = 3.0f * w1 / wsum, a2 = 3.0f * w2 / wsum;

    float tmp[4];
    #pragma unroll
    for (int i = 0; i < 4; i++)
        tmp[i] = fmaxf(a0 * low[i] + a1 * high[i] + a2 * mlp[i], 0.f);

    uint2 hv, lv;
    split4(tmp, hv, lv);
    const size_t off = base / 4;
    ((uint2*)Ahi)[off] = hv;
    ((uint2*)Alo)[off] = lv;
}

// ------------- layer-2 fused spmm + attention (interleaved gather) ---------
// hlh: [N][128] with cols [0:64)=low-proj (hl), [64:128)=high-proj (hh).
// Lanes 0-15 handle the low half, lanes 16-31 the high half; halves are
// recombined with shfl_xor(16) at the end.

__global__ __launch_bounds__(256)
void acm_fuse64(const float* __restrict__ hlh, const float* __restrict__ hm,
                const int* __restrict__ rowptr, const int* __restrict__ col,
                const float* __restrict__ vl, const float* __restrict__ vh,
                const float* __restrict__ vm, const float* __restrict__ av,
                float* __restrict__ out, int n) {
    int gw = (blockIdx.x * blockDim.x + threadIdx.x) >> 5;
    if (gw >= n) return;
    const int lane = threadIdx.x & 31;
    const int s = rowptr[gw], e = rowptr[gw + 1];
    const bool hiHalf = lane >= 16;

    float acc[4] = {0.f, 0.f, 0.f, 0.f};

    for (int base = s; base < e; base += 32) {
        int idx = base + lane;
        int c = (idx < e) ? col[idx] : 0;
        int cnt = min(32, e - base);
        int k = 0;
        for (; k + 8 <= cnt; k += 8) {
            float4 v[8];
            #pragma unroll
            for (int j = 0; j < 8; j++) {
                int cc = __shfl_sync(0xffffffffu, c, k + j);
                v[j] = *(const float4*)(hlh + (size_t)cc * 128 + lane * 4);
            }
            #pragma unroll
            for (int j = 0; j < 8; j++) {
                acc[0] += v[j].x; acc[1] += v[j].y; acc[2] += v[j].z; acc[3] += v[j].w;
            }
        }
        for (; k < cnt; k++) {
            int cc = __shfl_sync(0xffffffffu, c, k);
            float4 v = *(const float4*)(hlh + (size_t)cc * 128 + lane * 4);
            acc[0] += v.x; acc[1] += v.y; acc[2] += v.z; acc[3] += v.w;
        }
    }

    const float inv = (e > s) ? 1.0f / (float)(e - s) : 0.0f;

    float4 own4 = *(const float4*)(hlh + (size_t)gw * 128 + lane * 4);
    float4 ml4 = *(const float4*)(hm + (size_t)gw * 64 + (lane & 15) * 4);
    float own[4] = {own4.x, own4.y, own4.z, own4.w};
    float mlp[4] = {ml4.x, ml4.y, ml4.z, ml4.w};

    float val[4];
    #pragma unroll
    for (int j = 0; j < 4; j++) {
        float a = inv * acc[j];
        val[j] = hiHalf ? fmaxf(own[j] - a, 0.f) : fmaxf(a, 0.f);
    }

    float dl = 0.f, dh = 0.f, dm = 0.f;
    if (!hiHalf) {
        #pragma unroll
        for (int j = 0; j < 4; j++) {
            dl += val[j] * vl[lane * 4 + j];
            dm += mlp[j] * vm[lane * 4 + j];
        }
    } else {
        #pragma unroll
        for (int j = 0; j < 4; j++)
            dh += val[j] * vh[(lane - 16) * 4 + j];
    }
    #pragma unroll
    for (int o = 16; o > 0; o >>= 1) {
        dl += __shfl_xor_sync(0xffffffffu, dl, o);
        dh += __shfl_xor_sync(0xffffffffu, dh, o);
        dm += __shfl_xor_sync(0xffffffffu, dm, o);
    }

    float sl = 1.0f / (1.0f + __expf(-dl));
    float sh = 1.0f / (1.0f + __expf(-dh));
    float sm = 1.0f / (1.0f + __expf(-dm));

    float t0 = (sl * av[0] + sh * av[3] + sm * av[6]) * (1.0f / 3.0f);
    float t1 = (sl * av[1] + sh * av[4] + sm * av[7]) * (1.0f / 3.0f);
    float t2 = (sl * av[2] + sh * av[5] + sm * av[8]) * (1.0f / 3.0f);
    float mx = fmaxf(t0, fmaxf(t1, t2));
    float w0 = __expf(t0 - mx), w1 = __expf(t1 - mx), w2 = __expf(t2 - mx);
    float wsum = w0 + w1 + w2;
    float a0 = 3.0f * w0 / wsum, a1 = 3.0f * w1 / wsum, a2 = 3.0f * w2 / wsum;

    float part[4], other[4];
    #pragma unroll
    for (int j = 0; j < 4; j++)
        part[j] = hiHalf ? a1 * val[j] : a0 * val[j];
    #pragma unroll
    for (int j = 0; j < 4; j++)
        other[j] = __shfl_xor_sync(0xffffffffu, part[j], 16);

    if (!hiHalf) {
        float4 o4;
        o4.x = part[0] + other[0] + a2 * mlp[0];
        o4.y = part[1] + other[1] + a2 * mlp[1];
        o4.z = part[2] + other[2] + a2 * mlp[2];
        o4.w = part[3] + other[3] + a2 * mlp[3];
        *(float4*)(out + (size_t)gw * 64 + lane * 4) = o4;
    }
}

// ------------------------------ launch -------------------------------------

extern "C" void kernel_launch(void* const* d_in, const int* in_sizes, int n_in,
                              void* d_out, int out_size) {
    const float* x    = (const float*)d_in[0];
    const int*   ei   = (const int*)d_in[1];
    const float* Wl1  = (const float*)d_in[2];
    const float* Wh1  = (const float*)d_in[3];
    const float* Wm1  = (const float*)d_in[4];
    const float* vl1  = (const float*)d_in[5];
    const float* vh1  = (const float*)d_in[6];
    const float* vm1  = (const float*)d_in[7];
    const float* av1  = (const float*)d_in[8];
    const float* Wl2  = (const float*)d_in[9];
    const float* Wh2  = (const float*)d_in[10];
    const float* Wm2  = (const float*)d_in[11];
    const float* vl2  = (const float*)d_in[12];
    const float* vh2  = (const float*)d_in[13];
    const float* vm2  = (const float*)d_in[14];
    const float* av2  = (const float*)d_in[15];

    const int n = in_sizes[0] / 128;
    const int E = in_sizes[1] / 2;
    const int* row = ei;
    const int* colsrc = ei + E;

    int *deg, *fill, *rowptr, *col;
    float *hl, *hh, *hm;
    __nv_bfloat16 *ahi, *alo, *bhi, *blo, *chi, *clo, *wthi, *wtlo;
    cudaGetSymbolAddress((void**)&deg, g_deg);
    cudaGetSymbolAddress((void**)&fill, g_fill);
    cudaGetSymbolAddress((void**)&rowptr, g_rowptr);
    cudaGetSymbolAddress((void**)&col, g_col);
    cudaGetSymbolAddress((void**)&hl, g_hl);
    cudaGetSymbolAddress((void**)&hh, g_hh);
    cudaGetSymbolAddress((void**)&hm, g_hm);
    cudaGetSymbolAddress((void**)&ahi, g_ahi);
    cudaGetSymbolAddress((void**)&alo, g_alo);
    cudaGetSymbolAddress((void**)&bhi, g_bhi);
    cudaGetSymbolAddress((void**)&blo, g_blo);
    cudaGetSymbolAddress((void**)&chi, g_chi);
    cudaGetSymbolAddress((void**)&clo, g_clo);
    cudaGetSymbolAddress((void**)&wthi, g_wthi);
    cudaGetSymbolAddress((void**)&wtlo, g_wtlo);

    float* out = (float*)d_out;

    const int smem1 = (2 * 128 * 136 + 2 * 128 * 136) * 2;
    const int smem2 = (2 * 128 * 136 + 2 * 64 * 136) * 2;
    cudaFuncSetAttribute(gemm_mma<128>, cudaFuncAttributeMaxDynamicSharedMemorySize, smem1);
    cudaFuncSetAttribute(gemm_mma<64>, cudaFuncAttributeMaxDynamicSharedMemorySize, smem2);

    // CSR build
    zero_kernel<<<(n + 255) / 256, 256>>>(deg, fill, n);
    deg_kernel<<<(E + 255) / 256, 256>>>(row, deg, E);
    scan_kernel<<<1, 1024>>>(deg, rowptr, n);
    scatter_kernel<<<(E + 255) / 256, 256>>>(row, colsrc, rowptr, fill, col, E);

    const int gx = (n + 127) / 128;

    // ---- layer 1 ----
    conv_w_kernel<<<(3 * 128 * 128 + 255) / 256, 256>>>(Wl1, Wh1, Wm1, wthi, wtlo, 128, 128);
    spmm_cvt<<<(n + 7) / 8, 256>>>(x, rowptr, col, ahi, alo, bhi, blo, chi, clo, n);
    {
        dim3 grid(gx, 3);
        gemm_mma<128><<<grid, 256, smem1>>>(ahi, alo, bhi, blo, chi, clo,
                                            wthi, wtlo, hl, hh, hm,
                                            128, 128, 128, 0, 0, 0, n, 1);
    }
    att_fuse<<<(n + 7) / 8, 256>>>(hl, hh, hm, vl1, vh1, vm1, av1, ahi, alo, n);

    // ---- layer 2 ----
    conv_w_kernel<<<(3 * 128 * 64 + 255) / 256, 256>>>(Wl2, Wh2, Wm2, wthi, wtlo, 128, 64);
    {
        // low -> hl cols [0,64), high -> hl cols [64,128) (interleaved), mlp -> hm
        dim3 grid(gx, 3);
        gemm_mma<64><<<grid, 256, smem2>>>(ahi, alo, ahi, alo, ahi, alo,
                                           wthi, wtlo, hl, hl, hm,
                                           128, 128, 64, 0, 64, 0, n, 0);
    }
    acm_fuse64<<<(n + 7) / 8, 256>>>(hl, hm, rowptr, col,
                                     vl2, vh2, vm2, av2, out, n);
}